// round 1
// baseline (speedup 1.0000x reference)
#include <cuda_runtime.h>
#include <math.h>

// MHAStateEncoder — persistent-CTA fused kernel.
// B batches; per batch: agg/gather -> raw(192) -> q(128) -> per-head qk(8x64)
// -> scores(8x20) -> softmax -> attn-weighted node sums m(8x64) -> ctx(128) -> out(64).
// All weights resident in shared memory (loaded once per CTA).

#define NTHREADS 256
#define GRID_BLOCKS 148

// shared memory layout (in floats)
#define OFF_WQ     0          // 192*128 = 24576
#define OFF_WKT    24576      // 128*65  = 8320  (Wk transposed, padded stride 65)
#define OFF_WV     32896      // 64*128  = 8192
#define OFF_WO     41088      // 128*64  = 8192
#define OFF_BQ     49280      // 128
#define OFF_BV     49408      // 128
#define OFF_BO     49536      // 64
#define OFF_NT     49600      // nodesT [64][21] = 1344 (padded stride 21)
#define OFF_RAW    50944      // 192
#define OFF_Q      51136      // 128
#define OFF_QK     51264      // [8][68] = 544 (padded stride 68)
#define OFF_SC     51808      // 160 (scores -> attn)
#define OFF_M      51968      // [8][68] = 544
#define OFF_CTX    52512      // 128
#define OFF_RED    52640      // 256
#define OFF_VALID  52896      // 20
#define OFF_MASK   52916      // 20
#define SMEM_FLOATS 52936
#define SMEM_BYTES  (SMEM_FLOATS * 4)

__global__ void __launch_bounds__(NTHREADS, 1)
mha_state_encoder_kernel(const float* __restrict__ node_embed,
                         const int*   __restrict__ start_idx,
                         const int*   __restrict__ end_idx,
                         const int*   __restrict__ pad_idx,
                         const float* __restrict__ Wq, const float* __restrict__ bq,
                         const float* __restrict__ Wk,
                         const float* __restrict__ Wv, const float* __restrict__ bv,
                         const float* __restrict__ Wo, const float* __restrict__ bo,
                         float* __restrict__ out, int B)
{
    extern __shared__ float sm[];
    float* sWq    = sm + OFF_WQ;
    float* sWkT   = sm + OFF_WKT;
    float* sWv    = sm + OFF_WV;
    float* sWo    = sm + OFF_WO;
    float* sBq    = sm + OFF_BQ;
    float* sBv    = sm + OFF_BV;
    float* sBo    = sm + OFF_BO;
    float* sNT    = sm + OFF_NT;     // nodes transposed: [d][j], stride 21
    float* sRaw   = sm + OFF_RAW;    // [agg(64) | start(64) | end(64)]
    float* sQ     = sm + OFF_Q;
    float* sQK    = sm + OFF_QK;     // [h][d], stride 68
    float* sSc    = sm + OFF_SC;     // [h][j]
    float* sM     = sm + OFF_M;      // [h][d], stride 68
    float* sCtx   = sm + OFF_CTX;
    float* sRed   = sm + OFF_RED;
    float* sValid = sm + OFF_VALID;
    float* sMask  = sm + OFF_MASK;

    const int t = threadIdx.x;

    // ---- load weights into SMEM (once per CTA) ----
    for (int i = t; i < 24576 / 4; i += NTHREADS)
        reinterpret_cast<float4*>(sWq)[i] = reinterpret_cast<const float4*>(Wq)[i];
    for (int i = t; i < 8192; i += NTHREADS) {
        int d = i >> 7, c = i & 127;
        sWkT[c * 65 + d] = Wk[i];          // transpose: [c][d], padded
    }
    for (int i = t; i < 8192 / 4; i += NTHREADS) {
        reinterpret_cast<float4*>(sWv)[i] = reinterpret_cast<const float4*>(Wv)[i];
        reinterpret_cast<float4*>(sWo)[i] = reinterpret_cast<const float4*>(Wo)[i];
    }
    if (t < 128) { sBq[t] = bq[t]; sBv[t] = bv[t]; }
    if (t < 64)  sBo[t] = bo[t];

    // ---- software prefetch for first batch ----
    const int b0 = blockIdx.x;
    float4 pfA = make_float4(0.f, 0.f, 0.f, 0.f);
    float4 pfB = make_float4(0.f, 0.f, 0.f, 0.f);
    float  pg  = 0.f;       // prefetched gather element (start/end rows)
    int    pp  = 0;         // prefetched pad_idx
    int    gidx_n = 0;      // gather row index for the NEXT batch (loaded ahead)

    const int which = (t >> 6) & 1;   // for t in [128,256): 0 -> start row, 1 -> end row
    const int gd    = t & 63;

    if (b0 < B) {
        const float4* src = reinterpret_cast<const float4*>(node_embed + (size_t)b0 * 1280);
        pfA = src[t];
        if (t < 64) pfB = src[t + 256];
        if (t < 20) pp = pad_idx[b0 * 20 + t];
        if (t >= 128) {
            int gi = which ? end_idx[b0] : start_idx[b0];
            pg = node_embed[(size_t)gi * 64 + gd];
            int bn = b0 + GRID_BLOCKS;
            if (bn < B) gidx_n = which ? end_idx[bn] : start_idx[bn];
        }
    }
    __syncthreads();   // weights ready

    for (int b = b0; b < B; b += GRID_BLOCKS) {
        // ---- P1: commit prefetched data to SMEM ----
        {
            int i = t * 4, j = i >> 6, d = i & 63;
            sNT[(d + 0) * 21 + j] = pfA.x;
            sNT[(d + 1) * 21 + j] = pfA.y;
            sNT[(d + 2) * 21 + j] = pfA.z;
            sNT[(d + 3) * 21 + j] = pfA.w;
            if (t < 64) {
                int i2 = (t + 256) * 4, j2 = i2 >> 6, d2 = i2 & 63;
                sNT[(d2 + 0) * 21 + j2] = pfB.x;
                sNT[(d2 + 1) * 21 + j2] = pfB.y;
                sNT[(d2 + 2) * 21 + j2] = pfB.z;
                sNT[(d2 + 3) * 21 + j2] = pfB.w;
            }
            if (t < 20) sValid[t] = (pp >= 0) ? 1.0f : 0.0f;
            if (t >= 128) sRaw[64 + (which << 6) + gd] = pg;
        }
        __syncthreads();

        // ---- issue prefetch for next batch (latency hidden under this batch) ----
        {
            int bn = b + GRID_BLOCKS;
            if (bn < B) {
                const float4* src = reinterpret_cast<const float4*>(node_embed + (size_t)bn * 1280);
                pfA = src[t];
                if (t < 64) pfB = src[t + 256];
                if (t < 20) pp = pad_idx[bn * 20 + t];
                if (t >= 128) {
                    pg = node_embed[(size_t)gidx_n * 64 + gd];
                    int bnn = bn + GRID_BLOCKS;
                    if (bnn < B) gidx_n = which ? end_idx[bnn] : start_idx[bnn];
                }
            }
        }

        // ---- P2: agg (segment sum, UNmasked rows) + mask flags ----
        if (t < 64) {
            float s = 0.f;
            #pragma unroll
            for (int j = 0; j < 20; ++j) s += sNT[t * 21 + j];
            sRaw[t] = s;
        } else if (t < 84) {
            int j = t - 64;
            float s = 0.f;
            #pragma unroll
            for (int d = 0; d < 64; ++d) s += sNT[d * 21 + j];
            // ref: mask = (sum(masked_row) == 0)  ->  !valid || rowsum == 0
            sMask[j] = (sValid[j] == 0.f || s == 0.f) ? 1.0f : 0.0f;
        }
        __syncthreads();

        // ---- P3: q = raw @ Wq + bq   (split over 2 r-halves) ----
        {
            int c  = t & 127;
            int r0 = (t >> 7) * 96;
            const float* wq = sWq + c;
            float a0 = 0.f, a1 = 0.f, a2 = 0.f, a3 = 0.f;
            #pragma unroll
            for (int r = 0; r < 96; r += 4) {
                a0 = fmaf(sRaw[r0 + r + 0], wq[(r0 + r + 0) * 128], a0);
                a1 = fmaf(sRaw[r0 + r + 1], wq[(r0 + r + 1) * 128], a1);
                a2 = fmaf(sRaw[r0 + r + 2], wq[(r0 + r + 2) * 128], a2);
                a3 = fmaf(sRaw[r0 + r + 3], wq[(r0 + r + 3) * 128], a3);
            }
            sRed[t] = (a0 + a1) + (a2 + a3);
        }
        __syncthreads();
        if (t < 128) sQ[t] = sRed[t] + sRed[t + 128] + sBq[t];
        __syncthreads();

        // ---- P4: qk[h][d] = sum_i q[h*16+i] * Wk[d][h*16+i]   (bk cancels in softmax) ----
        #pragma unroll
        for (int u = t; u < 512; u += NTHREADS) {
            int h = u >> 6, d = u & 63;
            const float* wk = sWkT + d;
            const float* qh = sQ + h * 16;
            float a0 = 0.f, a1 = 0.f;
            #pragma unroll
            for (int i = 0; i < 16; i += 2) {
                a0 = fmaf(qh[i + 0], wk[(h * 16 + i + 0) * 65], a0);
                a1 = fmaf(qh[i + 1], wk[(h * 16 + i + 1) * 65], a1);
            }
            sQK[h * 68 + d] = a0 + a1;
        }
        __syncthreads();

        // ---- P5: scores[h][j] = 0.25 * qk[h] . nodes[j]  + mask*(-1e9) ----
        if (t < 160) {
            int h = t / 20, j = t - h * 20;
            const float* qk = sQK + h * 68;
            const float* nt = sNT + j;
            float a0 = 0.f, a1 = 0.f, a2 = 0.f, a3 = 0.f;
            #pragma unroll
            for (int d = 0; d < 64; d += 4) {
                a0 = fmaf(qk[d + 0], nt[(d + 0) * 21], a0);
                a1 = fmaf(qk[d + 1], nt[(d + 1) * 21], a1);
                a2 = fmaf(qk[d + 2], nt[(d + 2) * 21], a2);
                a3 = fmaf(qk[d + 3], nt[(d + 3) * 21], a3);
            }
            sSc[h * 20 + j] = ((a0 + a1) + (a2 + a3)) * 0.25f + sMask[j] * (-1e9f);
        }
        __syncthreads();

        // ---- softmax per head (fold valid factor into attn: v of invalid nodes is bv-only) ----
        if (t < 8) {
            float mx = -3.4e38f;
            #pragma unroll
            for (int j = 0; j < 20; ++j) mx = fmaxf(mx, sSc[t * 20 + j]);
            float ssum = 0.f;
            #pragma unroll
            for (int j = 0; j < 20; ++j) {
                float e = __expf(sSc[t * 20 + j] - mx);
                sSc[t * 20 + j] = e;
                ssum += e;
            }
            float inv = 1.0f / ssum;
            #pragma unroll
            for (int j = 0; j < 20; ++j) sSc[t * 20 + j] *= inv * sValid[j];
        }
        __syncthreads();

        // ---- P6: m[h][d] = sum_j attn[h][j] * nodes[j][d] ----
        #pragma unroll
        for (int u = t; u < 512; u += NTHREADS) {
            int h = u >> 6, d = u & 63;
            const float* at = sSc + h * 20;
            const float* nt = sNT + d * 21;
            float a0 = 0.f, a1 = 0.f;
            #pragma unroll
            for (int j = 0; j < 20; j += 2) {
                a0 = fmaf(at[j + 0], nt[j + 0], a0);
                a1 = fmaf(at[j + 1], nt[j + 1], a1);
            }
            sM[h * 68 + d] = a0 + a1;
        }
        __syncthreads();

        // ---- P7: ctx[c] = m[h(c)] . Wv[:,c] + bv[c]   (split over 2 d-halves) ----
        {
            int c  = t & 127;
            int dh = (t >> 7) * 32;
            const float* m  = sM + (c >> 4) * 68 + dh;
            const float* wv = sWv + dh * 128 + c;
            float a0 = 0.f, a1 = 0.f, a2 = 0.f, a3 = 0.f;
            #pragma unroll
            for (int d = 0; d < 32; d += 4) {
                a0 = fmaf(m[d + 0], wv[(d + 0) * 128], a0);
                a1 = fmaf(m[d + 1], wv[(d + 1) * 128], a1);
                a2 = fmaf(m[d + 2], wv[(d + 2) * 128], a2);
                a3 = fmaf(m[d + 3], wv[(d + 3) * 128], a3);
            }
            sRed[t] = (a0 + a1) + (a2 + a3);
        }
        __syncthreads();
        if (t < 128) sCtx[t] = sRed[t] + sRed[t + 128] + sBv[t];
        __syncthreads();

        // ---- P8: out[o] = ctx . Wo[:,o] + bo[o]   (split over 4 c-quarters) ----
        {
            int o  = t & 63;
            int c0 = (t >> 6) * 32;
            const float* cx = sCtx + c0;
            const float* wo = sWo + c0 * 64 + o;
            float a0 = 0.f, a1 = 0.f, a2 = 0.f, a3 = 0.f;
            #pragma unroll
            for (int c = 0; c < 32; c += 4) {
                a0 = fmaf(cx[c + 0], wo[(c + 0) * 64], a0);
                a1 = fmaf(cx[c + 1], wo[(c + 1) * 64], a1);
                a2 = fmaf(cx[c + 2], wo[(c + 2) * 64], a2);
                a3 = fmaf(cx[c + 3], wo[(c + 3) * 64], a3);
            }
            sRed[t] = (a0 + a1) + (a2 + a3);
        }
        __syncthreads();
        if (t < 64)
            out[(size_t)b * 64 + t] =
                ((sRed[t] + sRed[t + 64]) + (sRed[t + 128] + sRed[t + 192])) + sBo[t];
        // no trailing barrier needed: next-iteration writes to these buffers occur
        // only after at least one __syncthreads in the next iteration.
    }
}

extern "C" void kernel_launch(void* const* d_in, const int* in_sizes, int n_in,
                              void* d_out, int out_size)
{
    const float* node_embed = (const float*)d_in[0];
    const int*   start_idx  = (const int*)d_in[1];
    const int*   end_idx    = (const int*)d_in[2];
    /* d_in[3] = seg_ids : structurally arange(N)/MAX_NODES, unused */
    const int*   pad_idx    = (const int*)d_in[4];
    const float* Wq         = (const float*)d_in[5];
    const float* bq         = (const float*)d_in[6];
    const float* Wk         = (const float*)d_in[7];
    /* d_in[8] = bk : cancels inside softmax (constant per-head shift), unused */
    const float* Wv         = (const float*)d_in[9];
    const float* bv         = (const float*)d_in[10];
    const float* Wo         = (const float*)d_in[11];
    const float* bo         = (const float*)d_in[12];
    float* out = (float*)d_out;

    int B = out_size / 64;

    cudaFuncSetAttribute(mha_state_encoder_kernel,
                         cudaFuncAttributeMaxDynamicSharedMemorySize, SMEM_BYTES);
    mha_state_encoder_kernel<<<GRID_BLOCKS, NTHREADS, SMEM_BYTES>>>(
        node_embed, start_idx, end_idx, pad_idx,
        Wq, bq, Wk, Wv, bv, Wo, bo, out, B);
}

// round 2
// speedup vs baseline: 1.8879x; 1.8879x over previous
#include <cuda_runtime.h>
#include <math.h>

// MHAStateEncoder — persistent-CTA fused kernel, Round 2.
// NB=4 batches per loop iteration; Wq register-resident; dual node layouts;
// float4-vectorized shared traffic; weights (WkT/Wv/Wo) in SMEM shared across
// the 4 batches of an iteration.

#define NT 256
#define GRID 148

// shared memory offsets (floats)
#define OFF_WKT   0        // [128][65]  WkT[c][d] = Wk[d][c]
#define OFF_WV    8320     // [64][128]  natural
#define OFF_WO    16512    // [128][64]  natural
#define OFF_BQ    24704    // 128
#define OFF_BV    24832    // 128
#define OFF_BO    24960    // 64
#define OFF_N     25024    // [nb][20][68]  nodes row-major, padded
#define OFF_NT    30464    // [nb][64][21]  nodes transposed, padded
#define OFF_RAW   35840    // [nb][192]  [agg | start | end]
#define OFF_Q     36608    // [nb][128]
#define OFF_QK    37120    // [nb][8][72]
#define OFF_SC    39424    // [nb][8][24]
#define OFF_M     40192    // [nb][8][72]
#define OFF_CTX   42496    // [nb][128]
#define OFF_RED   43008    // 1024 scratch reductions
#define OFF_VALID 44032    // [nb][20]
#define OFF_MASK  44112    // [nb][20]
#define SMEM_FLOATS 44192
#define SMEM_BYTES  (SMEM_FLOATS * 4)

__global__ void __launch_bounds__(NT, 1)
mha_state_encoder_kernel(const float* __restrict__ node_embed,
                         const int*   __restrict__ start_idx,
                         const int*   __restrict__ end_idx,
                         const int*   __restrict__ pad_idx,
                         const float* __restrict__ Wq, const float* __restrict__ bq,
                         const float* __restrict__ Wk,
                         const float* __restrict__ Wv, const float* __restrict__ bv,
                         const float* __restrict__ Wo, const float* __restrict__ bo,
                         float* __restrict__ out, int B)
{
    extern __shared__ float sm[];
    float* sWKT   = sm + OFF_WKT;
    float* sWV    = sm + OFF_WV;
    float* sWO    = sm + OFF_WO;
    float* sBQ    = sm + OFF_BQ;
    float* sBV    = sm + OFF_BV;
    float* sBO    = sm + OFF_BO;
    float* sN     = sm + OFF_N;
    float* sNT    = sm + OFF_NT;
    float* sRAW   = sm + OFF_RAW;
    float* sQ     = sm + OFF_Q;
    float* sQK    = sm + OFF_QK;
    float* sSC    = sm + OFF_SC;
    float* sM     = sm + OFF_M;
    float* sCTX   = sm + OFF_CTX;
    float* sRED   = sm + OFF_RED;
    float* sVALID = sm + OFF_VALID;
    float* sMASK  = sm + OFF_MASK;

    const int t = threadIdx.x;
    const int Q = B >> 2;                 // number of 4-batch quads

    // ---- weight staging ----
    // WkT transpose into smem
    for (int i = t; i < 8192; i += NT) {
        int d = i >> 7, c = i & 127;
        sWKT[c * 65 + d] = Wk[i];
    }
    for (int i = t; i < 8192 / 4; i += NT) {
        reinterpret_cast<float4*>(sWV)[i] = reinterpret_cast<const float4*>(Wv)[i];
        reinterpret_cast<float4*>(sWO)[i] = reinterpret_cast<const float4*>(Wo)[i];
    }
    if (t < 128) { sBQ[t] = bq[t]; sBV[t] = bv[t]; }
    if (t < 64)  sBO[t] = bo[t];

    // Wq register slice: column c = t&127, rows rh*96 .. rh*96+95
    const int c127 = t & 127;
    const int rh   = t >> 7;
    float wq[96];
    {
        const float* src = Wq + (size_t)(rh * 96) * 128 + c127;
        #pragma unroll
        for (int i = 0; i < 96; ++i) wq[i] = src[(size_t)i * 128];
    }

    // gather-thread geometry (threads 128..255)
    const int gidx  = t - 128;            // 0..127 for t>=128
    const int gnb   = (gidx >> 5) & 3;    // batch within quad
    const int gwh   = (gidx >> 4) & 1;    // 0=start, 1=end
    const int gdq   = gidx & 15;          // d-quad

    // ---- prefetch state ----
    float4 pfN[5];
    float4 pfG = make_float4(0.f, 0.f, 0.f, 0.f);
    int    pfP = 0;
    int    gi_next = 0;

    int q0 = blockIdx.x;
    if (q0 < Q) {
        int b0 = q0 * 4;
        const float4* nsrc = reinterpret_cast<const float4*>(node_embed) + (size_t)b0 * 320;
        #pragma unroll
        for (int k = 0; k < 5; ++k) pfN[k] = nsrc[t + k * 256];
        if (t < 80) pfP = pad_idx[b0 * 20 + t];
        if (t >= 128) {
            int gi = gwh ? end_idx[b0 + gnb] : start_idx[b0 + gnb];
            pfG = *reinterpret_cast<const float4*>(node_embed + (size_t)gi * 64 + gdq * 4);
            int qn = q0 + GRID;
            if (qn < Q) gi_next = gwh ? end_idx[qn * 4 + gnb] : start_idx[qn * 4 + gnb];
        }
    }
    __syncthreads();   // weights staged

    for (int q = q0; q < Q; q += GRID) {
        const int b0 = q * 4;

        // ================= P1: commit prefetched data =================
        {
            float4* sN4 = reinterpret_cast<float4*>(sN);
            #pragma unroll
            for (int k = 0; k < 5; ++k) {
                int g   = t + k * 256;        // float4 index within 1280
                int nb  = g / 320;
                int rem = g - nb * 320;
                int j   = rem >> 4;
                int dq  = rem & 15;
                sN4[nb * 340 + j * 17 + dq] = pfN[k];
                float* nt = sNT + nb * 1344 + (dq * 4) * 21 + j;
                nt[0]  = pfN[k].x;
                nt[21] = pfN[k].y;
                nt[42] = pfN[k].z;
                nt[63] = pfN[k].w;
            }
            if (t < 80) sVALID[t] = (pfP >= 0) ? 1.0f : 0.0f;
            if (t >= 128)
                *reinterpret_cast<float4*>(sRAW + gnb * 192 + 64 + gwh * 64 + gdq * 4) = pfG;
        }

        // ---- issue prefetch for next quad (latency hidden under this one) ----
        {
            int qn = q + GRID;
            if (qn < Q) {
                int bn = qn * 4;
                const float4* nsrc = reinterpret_cast<const float4*>(node_embed) + (size_t)bn * 320;
                #pragma unroll
                for (int k = 0; k < 5; ++k) pfN[k] = nsrc[t + k * 256];
                if (t < 80) pfP = pad_idx[bn * 20 + t];
                if (t >= 128) {
                    pfG = *reinterpret_cast<const float4*>(node_embed + (size_t)gi_next * 64 + gdq * 4);
                    int qn2 = qn + GRID;
                    if (qn2 < Q) gi_next = gwh ? end_idx[qn2 * 4 + gnb] : start_idx[qn2 * 4 + gnb];
                }
            }
        }
        __syncthreads();

        // ================= P2: agg + mask =================
        {
            int nb = t >> 6, d = t & 63;
            const float* nt = sNT + nb * 1344 + d * 21;
            float s0 = 0.f, s1 = 0.f;
            #pragma unroll
            for (int j = 0; j < 20; j += 2) { s0 += nt[j]; s1 += nt[j + 1]; }
            sRAW[nb * 192 + d] = s0 + s1;

            if (t < 80) {
                int nb2 = t / 20, j2 = t - nb2 * 20;
                const float4* row = reinterpret_cast<const float4*>(sN + nb2 * 1360 + j2 * 68);
                float r0 = 0.f, r1 = 0.f;
                #pragma unroll
                for (int k = 0; k < 16; k += 2) {
                    float4 a = row[k], b = row[k + 1];
                    r0 += (a.x + a.y) + (a.z + a.w);
                    r1 += (b.x + b.y) + (b.z + b.w);
                }
                float rsum = r0 + r1;
                sMASK[t] = (sVALID[t] == 0.f || rsum == 0.f) ? 1.0f : 0.0f;
            }
        }
        __syncthreads();

        // ================= P3: q = raw @ Wq (Wq in registers) =================
        {
            const float4* rv0 = reinterpret_cast<const float4*>(sRAW + 0 * 192 + rh * 96);
            const float4* rv1 = reinterpret_cast<const float4*>(sRAW + 1 * 192 + rh * 96);
            const float4* rv2 = reinterpret_cast<const float4*>(sRAW + 2 * 192 + rh * 96);
            const float4* rv3 = reinterpret_cast<const float4*>(sRAW + 3 * 192 + rh * 96);
            float a0 = 0.f, a1 = 0.f, a2 = 0.f, a3 = 0.f;
            #pragma unroll
            for (int rq = 0; rq < 24; ++rq) {
                float4 x0 = rv0[rq], x1 = rv1[rq], x2 = rv2[rq], x3 = rv3[rq];
                const int i = rq * 4;
                a0 = fmaf(wq[i+0], x0.x, a0); a0 = fmaf(wq[i+1], x0.y, a0);
                a0 = fmaf(wq[i+2], x0.z, a0); a0 = fmaf(wq[i+3], x0.w, a0);
                a1 = fmaf(wq[i+0], x1.x, a1); a1 = fmaf(wq[i+1], x1.y, a1);
                a1 = fmaf(wq[i+2], x1.z, a1); a1 = fmaf(wq[i+3], x1.w, a1);
                a2 = fmaf(wq[i+0], x2.x, a2); a2 = fmaf(wq[i+1], x2.y, a2);
                a2 = fmaf(wq[i+2], x2.z, a2); a2 = fmaf(wq[i+3], x2.w, a2);
                a3 = fmaf(wq[i+0], x3.x, a3); a3 = fmaf(wq[i+1], x3.y, a3);
                a3 = fmaf(wq[i+2], x3.z, a3); a3 = fmaf(wq[i+3], x3.w, a3);
            }
            sRED[(rh * 4 + 0) * 128 + c127] = a0;
            sRED[(rh * 4 + 1) * 128 + c127] = a1;
            sRED[(rh * 4 + 2) * 128 + c127] = a2;
            sRED[(rh * 4 + 3) * 128 + c127] = a3;
        }
        __syncthreads();
        {
            #pragma unroll
            for (int e = t; e < 512; e += NT) {
                int nb = e >> 7, cc = e & 127;
                sQ[nb * 128 + cc] = sRED[nb * 128 + cc] + sRED[(4 + nb) * 128 + cc] + sBQ[cc];
            }
        }
        __syncthreads();

        // ================= P4: qk[h][d] = sum_i q[h*16+i] * WkT[h*16+i][d] ====
        {
            #pragma unroll
            for (int u = t; u < 512; u += NT) {
                int h = u >> 6, d = u & 63;
                const float* wk = sWKT + (h * 16) * 65 + d;
                float b0 = 0.f, b1 = 0.f, b2 = 0.f, b3 = 0.f;
                #pragma unroll
                for (int iq = 0; iq < 4; ++iq) {
                    float w0 = wk[(iq*4+0)*65], w1 = wk[(iq*4+1)*65];
                    float w2 = wk[(iq*4+2)*65], w3 = wk[(iq*4+3)*65];
                    float4 q0v = *reinterpret_cast<const float4*>(sQ + 0*128 + h*16 + iq*4);
                    float4 q1v = *reinterpret_cast<const float4*>(sQ + 1*128 + h*16 + iq*4);
                    float4 q2v = *reinterpret_cast<const float4*>(sQ + 2*128 + h*16 + iq*4);
                    float4 q3v = *reinterpret_cast<const float4*>(sQ + 3*128 + h*16 + iq*4);
                    b0 = fmaf(w0,q0v.x,b0); b0 = fmaf(w1,q0v.y,b0); b0 = fmaf(w2,q0v.z,b0); b0 = fmaf(w3,q0v.w,b0);
                    b1 = fmaf(w0,q1v.x,b1); b1 = fmaf(w1,q1v.y,b1); b1 = fmaf(w2,q1v.z,b1); b1 = fmaf(w3,q1v.w,b1);
                    b2 = fmaf(w0,q2v.x,b2); b2 = fmaf(w1,q2v.y,b2); b2 = fmaf(w2,q2v.z,b2); b2 = fmaf(w3,q2v.w,b2);
                    b3 = fmaf(w0,q3v.x,b3); b3 = fmaf(w1,q3v.y,b3); b3 = fmaf(w2,q3v.z,b3); b3 = fmaf(w3,q3v.w,b3);
                }
                sQK[0*576 + h*72 + d] = b0;
                sQK[1*576 + h*72 + d] = b1;
                sQK[2*576 + h*72 + d] = b2;
                sQK[3*576 + h*72 + d] = b3;
            }
        }
        __syncthreads();

        // ================= P5: scores[nb][h][j] = 0.25*qk[h].n[j] - mask ======
        {
            #pragma unroll
            for (int v = t; v < 640; v += NT) {
                int nb = v / 160;
                int r  = v - nb * 160;
                int h  = r / 20;
                int j  = r - h * 20;
                const float4* qk4 = reinterpret_cast<const float4*>(sQK + nb*576 + h*72);
                const float4* n4  = reinterpret_cast<const float4*>(sN  + nb*1360 + j*68);
                float s0 = 0.f, s1 = 0.f;
                #pragma unroll
                for (int k = 0; k < 16; k += 2) {
                    float4 a = qk4[k],   x = n4[k];
                    float4 b = qk4[k+1], y = n4[k+1];
                    s0 = fmaf(a.x,x.x,s0); s0 = fmaf(a.y,x.y,s0);
                    s0 = fmaf(a.z,x.z,s0); s0 = fmaf(a.w,x.w,s0);
                    s1 = fmaf(b.x,y.x,s1); s1 = fmaf(b.y,y.y,s1);
                    s1 = fmaf(b.z,y.z,s1); s1 = fmaf(b.w,y.w,s1);
                }
                sSC[nb*192 + h*24 + j] = (s0 + s1) * 0.25f + sMASK[nb*20 + j] * (-1e9f);
            }
        }
        __syncthreads();

        // ================= softmax per (nb, head) =================
        if (t < 32) {
            int nb = t >> 3, h = t & 7;
            float* row = sSC + nb * 192 + h * 24;
            const float* vd = sVALID + nb * 20;
            float mx = row[0];
            #pragma unroll
            for (int j = 1; j < 20; ++j) mx = fmaxf(mx, row[j]);
            float ssum = 0.f;
            #pragma unroll
            for (int j = 0; j < 20; ++j) {
                float e = __expf(row[j] - mx);
                row[j] = e;
                ssum += e;
            }
            float inv = 1.0f / ssum;
            #pragma unroll
            for (int j = 0; j < 20; ++j) row[j] = row[j] * inv * vd[j];
        }
        __syncthreads();

        // ================= P6: m[nb][h][d] = sum_j attn*n[j][d] ===============
        {
            #pragma unroll
            for (int u = t; u < 512; u += NT) {
                int dq = u & 15, h = (u >> 4) & 7, nb = u >> 7;
                const float* arow = sSC + nb * 192 + h * 24;
                const float4* n4  = reinterpret_cast<const float4*>(sN + nb * 1360);
                float mx_ = 0.f, my_ = 0.f, mz_ = 0.f, mw_ = 0.f;
                #pragma unroll
                for (int jq = 0; jq < 5; ++jq) {
                    float4 a  = *reinterpret_cast<const float4*>(arow + jq * 4);
                    float4 b0 = n4[(jq*4+0)*17 + dq];
                    float4 b1 = n4[(jq*4+1)*17 + dq];
                    float4 b2 = n4[(jq*4+2)*17 + dq];
                    float4 b3 = n4[(jq*4+3)*17 + dq];
                    mx_ = fmaf(a.x,b0.x,mx_); my_ = fmaf(a.x,b0.y,my_); mz_ = fmaf(a.x,b0.z,mz_); mw_ = fmaf(a.x,b0.w,mw_);
                    mx_ = fmaf(a.y,b1.x,mx_); my_ = fmaf(a.y,b1.y,my_); mz_ = fmaf(a.y,b1.z,mz_); mw_ = fmaf(a.y,b1.w,mw_);
                    mx_ = fmaf(a.z,b2.x,mx_); my_ = fmaf(a.z,b2.y,my_); mz_ = fmaf(a.z,b2.z,mz_); mw_ = fmaf(a.z,b2.w,mw_);
                    mx_ = fmaf(a.w,b3.x,mx_); my_ = fmaf(a.w,b3.y,my_); mz_ = fmaf(a.w,b3.z,mz_); mw_ = fmaf(a.w,b3.w,mw_);
                }
                *reinterpret_cast<float4*>(sM + nb*576 + h*72 + dq*4) = make_float4(mx_, my_, mz_, mw_);
            }
        }
        __syncthreads();

        // ================= P7: ctx[nb][c] = m[h(c)] . Wv[:,c] + bv =============
        {
            int cc = t & 127, dh = t >> 7, d0 = dh * 32, h = cc >> 4;
            const float* wv = sWV + d0 * 128 + cc;
            float a0 = 0.f, a1 = 0.f, a2 = 0.f, a3 = 0.f;
            #pragma unroll
            for (int k = 0; k < 8; ++k) {
                float w0 = wv[(k*4+0)*128], w1 = wv[(k*4+1)*128];
                float w2 = wv[(k*4+2)*128], w3 = wv[(k*4+3)*128];
                float4 m0 = *reinterpret_cast<const float4*>(sM + 0*576 + h*72 + d0 + k*4);
                float4 m1 = *reinterpret_cast<const float4*>(sM + 1*576 + h*72 + d0 + k*4);
                float4 m2 = *reinterpret_cast<const float4*>(sM + 2*576 + h*72 + d0 + k*4);
                float4 m3 = *reinterpret_cast<const float4*>(sM + 3*576 + h*72 + d0 + k*4);
                a0 = fmaf(w0,m0.x,a0); a0 = fmaf(w1,m0.y,a0); a0 = fmaf(w2,m0.z,a0); a0 = fmaf(w3,m0.w,a0);
                a1 = fmaf(w0,m1.x,a1); a1 = fmaf(w1,m1.y,a1); a1 = fmaf(w2,m1.z,a1); a1 = fmaf(w3,m1.w,a1);
                a2 = fmaf(w0,m2.x,a2); a2 = fmaf(w1,m2.y,a2); a2 = fmaf(w2,m2.z,a2); a2 = fmaf(w3,m2.w,a2);
                a3 = fmaf(w0,m3.x,a3); a3 = fmaf(w1,m3.y,a3); a3 = fmaf(w2,m3.z,a3); a3 = fmaf(w3,m3.w,a3);
            }
            sRED[(dh*4 + 0) * 128 + cc] = a0;
            sRED[(dh*4 + 1) * 128 + cc] = a1;
            sRED[(dh*4 + 2) * 128 + cc] = a2;
            sRED[(dh*4 + 3) * 128 + cc] = a3;
        }
        __syncthreads();
        {
            #pragma unroll
            for (int e = t; e < 512; e += NT) {
                int nb = e >> 7, cc = e & 127;
                sCTX[nb * 128 + cc] = sRED[nb * 128 + cc] + sRED[(4 + nb) * 128 + cc] + sBV[cc];
            }
        }
        __syncthreads();

        // ================= P8: out[nb][o] = ctx . Wo[:,o] + bo =================
        {
            int o = t & 63, cg = t >> 6, c0 = cg * 32;
            const float* wo = sWO + c0 * 64 + o;
            float a0 = 0.f, a1 = 0.f, a2 = 0.f, a3 = 0.f;
            #pragma unroll
            for (int k = 0; k < 8; ++k) {
                float w0 = wo[(k*4+0)*64], w1 = wo[(k*4+1)*64];
                float w2 = wo[(k*4+2)*64], w3 = wo[(k*4+3)*64];
                float4 x0 = *reinterpret_cast<const float4*>(sCTX + 0*128 + c0 + k*4);
                float4 x1 = *reinterpret_cast<const float4*>(sCTX + 1*128 + c0 + k*4);
                float4 x2 = *reinterpret_cast<const float4*>(sCTX + 2*128 + c0 + k*4);
                float4 x3 = *reinterpret_cast<const float4*>(sCTX + 3*128 + c0 + k*4);
                a0 = fmaf(w0,x0.x,a0); a0 = fmaf(w1,x0.y,a0); a0 = fmaf(w2,x0.z,a0); a0 = fmaf(w3,x0.w,a0);
                a1 = fmaf(w0,x1.x,a1); a1 = fmaf(w1,x1.y,a1); a1 = fmaf(w2,x1.z,a1); a1 = fmaf(w3,x1.w,a1);
                a2 = fmaf(w0,x2.x,a2); a2 = fmaf(w1,x2.y,a2); a2 = fmaf(w2,x2.z,a2); a2 = fmaf(w3,x2.w,a2);
                a3 = fmaf(w0,x3.x,a3); a3 = fmaf(w1,x3.y,a3); a3 = fmaf(w2,x3.z,a3); a3 = fmaf(w3,x3.w,a3);
            }
            sRED[(cg*4 + 0) * 64 + o] = a0;
            sRED[(cg*4 + 1) * 64 + o] = a1;
            sRED[(cg*4 + 2) * 64 + o] = a2;
            sRED[(cg*4 + 3) * 64 + o] = a3;
        }
        __syncthreads();
        {
            int nb = t >> 6, o = t & 63;
            float s = ((sRED[(0*4+nb)*64+o] + sRED[(1*4+nb)*64+o]) +
                       (sRED[(2*4+nb)*64+o] + sRED[(3*4+nb)*64+o])) + sBO[o];
            out[(size_t)(b0 + nb) * 64 + o] = s;
        }
        // no trailing sync: next-iter P1 writes regions whose last readers are
        // >=2 barriers earlier; P8-final reads only sRED/sBO (untouched by P1).
    }
}

extern "C" void kernel_launch(void* const* d_in, const int* in_sizes, int n_in,
                              void* d_out, int out_size)
{
    const float* node_embed = (const float*)d_in[0];
    const int*   start_idx  = (const int*)d_in[1];
    const int*   end_idx    = (const int*)d_in[2];
    /* d_in[3] = seg_ids : structurally arange(N)/MAX_NODES, unused */
    const int*   pad_idx    = (const int*)d_in[4];
    const float* Wq         = (const float*)d_in[5];
    const float* bq         = (const float*)d_in[6];
    const float* Wk         = (const float*)d_in[7];
    /* d_in[8] = bk : cancels inside softmax (constant per-head shift), unused */
    const float* Wv         = (const float*)d_in[9];
    const float* bv         = (const float*)d_in[10];
    const float* Wo         = (const float*)d_in[11];
    const float* bo         = (const float*)d_in[12];
    float* out = (float*)d_out;

    int B = out_size / 64;

    cudaFuncSetAttribute(mha_state_encoder_kernel,
                         cudaFuncAttributeMaxDynamicSharedMemorySize, SMEM_BYTES);
    mha_state_encoder_kernel<<<GRID, NT, SMEM_BYTES>>>(
        node_embed, start_idx, end_idx, pad_idx,
        Wq, bq, Wk, Wv, bv, Wo, bo, out, B);
}